// round 5
// baseline (speedup 1.0000x reference)
#include <cuda_runtime.h>

#define Hdim  100
#define Gdim  400
#define T_IN  1000
#define T_TOT 1300
#define NB    4
#define NCTA  128
#define NTHR  800

// Unit-major permuted, k-pair-packed weights. o = 4*j + gt  (gt: i,f,g,o)
__device__ float2 g_W1P[50 * Gdim];    // W_hh1^T   [k2][o]
__device__ float2 g_W2P[100 * Gdim];   // [W_ih2;W_hh2]^T [k2][o]
__device__ float  g_b1[Gdim], g_b2[Gdim], g_wi[Gdim];

__global__ void prep_weights(const float* __restrict__ W_hh1,
                             const float* __restrict__ W_ih2,
                             const float* __restrict__ W_hh2,
                             const float* __restrict__ W_ih1,
                             const float* __restrict__ b_ih1,
                             const float* __restrict__ b_hh1,
                             const float* __restrict__ b_ih2,
                             const float* __restrict__ b_hh2) {
    int i = blockIdx.x * blockDim.x + threadIdx.x;
    if (i < 50 * Gdim) {
        int k2 = i / Gdim, o = i % Gdim;
        int j = o >> 2, gt = o & 3, g = gt * Hdim + j;   // orig row
        g_W1P[i] = make_float2(W_hh1[g*Hdim + 2*k2], W_hh1[g*Hdim + 2*k2 + 1]);
    } else if (i < 150 * Gdim) {
        int q = i - 50 * Gdim;
        int k2 = q / Gdim, o = q % Gdim, k = 2 * k2;
        int j = o >> 2, gt = o & 3, g = gt * Hdim + j;
        g_W2P[q] = (k < Hdim)
            ? make_float2(W_ih2[g*Hdim + k],          W_ih2[g*Hdim + k + 1])
            : make_float2(W_hh2[g*Hdim + k - Hdim],   W_hh2[g*Hdim + k - Hdim + 1]);
    }
    if (i < Gdim) {
        int j = i >> 2, gt = i & 3, g = gt * Hdim + j;
        g_b1[i] = b_ih1[g] + b_hh1[g];
        g_b2[i] = b_ih2[g] + b_hh2[g];
        g_wi[i] = W_ih1[g];
    }
}

typedef unsigned long long u64;
typedef ulonglong2 u64x2;

__device__ __forceinline__ u64 pack2(float v) {
    u64 r; asm("mov.b64 %0, {%1, %1};" : "=l"(r) : "f"(v)); return r;
}
__device__ __forceinline__ void unpack2(u64 v, float& a, float& b) {
    asm("mov.b64 {%0, %1}, %2;" : "=f"(a), "=f"(b) : "l"(v));
}
__device__ __forceinline__ void fma2(u64& a, u64 w, u64 h) {
    asm("fma.rn.f32x2 %0, %1, %2, %0;" : "+l"(a) : "l"(w), "l"(h));
}
__device__ __forceinline__ u64 add2(u64 a, u64 b) {
    u64 r; asm("add.rn.f32x2 %0, %1, %2;" : "=l"(r) : "l"(a), "l"(b)); return r;
}
__device__ __forceinline__ float tanhfast(float x) {
    float y; asm("tanh.approx.f32 %0, %1;" : "=f"(y) : "f"(x)); return y;
}
__device__ __forceinline__ float sigfast(float x) {
    return fmaf(0.5f, tanhfast(0.5f * x), 0.5f);
}

__global__ __launch_bounds__(NTHR, 1)
void lstm2_kernel(const float* __restrict__ input,
                  const float* __restrict__ W_lin,
                  const float* __restrict__ b_lin,
                  float* __restrict__ out)
{
    extern __shared__ float sm[];
    float2* W1s   = (float2*)sm;                 // [50*400]  (40000 floats)
    float4* hbuf  = (float4*)(sm + 40000);       // [2][200]  ping-pong (1600 f)
    float4* gex   = (float4*)(sm + 41600);       // [25*16]   warp-local (1600 f)
    float4* xin   = (float4*)(sm + 43200);       // [1000]    input t-major (4000 f)
    float4* ysv   = (float4*)(sm + 47200);       // [1]
    float*  wlin  = sm + 47204;                  // [100]
    // total 47304 floats = 189216 B

    const int tid = threadIdx.x;
    const int w   = tid >> 5;
    const int l   = tid & 31;
    const int o   = w * 16 + (l >> 1);   // output index (unit-major)
    const int khalf = l & 1;
    const int b0  = blockIdx.x * NB;

    // ---- one-time init ----
    for (int i = tid; i < 50 * Gdim * 2; i += NTHR) ((float*)W1s)[i] = ((const float*)g_W1P)[i];
    for (int i = tid; i < 2 * 200 * 4; i += NTHR) ((float*)hbuf)[i] = 0.f;
    for (int i = tid; i < NB * T_IN; i += NTHR) {
        int t = i >> 2, b = i & 3;
        ((float*)xin)[i] = input[(b0 + b) * T_IN + t];
    }
    if (tid < Hdim) wlin[tid] = W_lin[tid];
    const float blin_r = __ldg(b_lin);

    const u64 bb1p = pack2(g_b1[o]);
    const u64 bb2p = pack2(g_b2[o]);
    const u64 wip  = pack2(g_wi[o]);
    const int kb1  = khalf * 25;     // layer-1 k2 range start
    const int kb2  = khalf * 50;     // layer-2 k2 range start
    const float2* wp2 = g_W2P + o;

    float4* gexw = gex + w * 16;
    const int ul = l >> 2, bl = l & 3;       // cell role (l < 16)
    float c1 = 0.f, c2 = 0.f;

    float4* hPrev = hbuf + 200;   // zeroed, holds h(-1)
    float4* hCur  = hbuf;
    __syncthreads();

    for (int t = 0; t < T_TOT; ++t) {
        u64 a0, a1;
        // ================= Layer 1 gates =================
        {
            if (!khalf) {
                const u64x2 xp = (t < T_IN) ? *(const u64x2*)(xin + t)
                                            : *(const u64x2*)ysv;
                a0 = bb1p; a1 = bb1p;
                fma2(a0, wip, xp.x); fma2(a1, wip, xp.y);
            } else { a0 = 0ull; a1 = 0ull; }
            const float2* wp = W1s + o;
            #pragma unroll 5
            for (int k2 = kb1; k2 < kb1 + 25; ++k2) {
                const float2 wv = wp[k2 * Gdim];
                const u64 w0 = pack2(wv.x), w1v = pack2(wv.y);
                const u64x2 h0 = *(const u64x2*)(hPrev + 2*k2);
                const u64x2 h1 = *(const u64x2*)(hPrev + 2*k2 + 1);
                fma2(a0, w0,  h0.x); fma2(a1, w0,  h0.y);
                fma2(a0, w1v, h1.x); fma2(a1, w1v, h1.y);
            }
        }
        // prefetch first W2 chunk (independent of the barrier below)
        float2 wb[5];
        #pragma unroll
        for (int p = 0; p < 5; ++p) wb[p] = __ldg(wp2 + (kb2 + p) * Gdim);

        // ---- combine k-halves + warp-local cell (h1 -> hCur) ----
        a0 = add2(a0, __shfl_xor_sync(0xffffffffu, a0, 1));
        a1 = add2(a1, __shfl_xor_sync(0xffffffffu, a1, 1));
        __syncwarp();
        if (!khalf) {
            float f0,f1,f2,f3; unpack2(a0,f0,f1); unpack2(a1,f2,f3);
            gexw[l >> 1] = make_float4(f0,f1,f2,f3);
        }
        __syncwarp();
        if (l < 16) {
            const float* gw = (const float*)(gexw + ul * 4);
            const float vi = gw[ 0 + bl], vf = gw[ 4 + bl];
            const float vg = gw[ 8 + bl], vo = gw[12 + bl];
            c1 = fmaf(sigfast(vf), c1, sigfast(vi) * tanhfast(vg));
            ((float*)hCur)[(w*4 + ul)*4 + bl] = sigfast(vo) * tanhfast(c1);
        }
        __syncthreads();   // h1(t) ready

        // ================= Layer 2 gates (k-split: h1 | h2) =================
        {
            if (!khalf) { a0 = bb2p; a1 = bb2p; } else { a0 = 0ull; a1 = 0ull; }
            const float4* hb = khalf ? hPrev : hCur;   // khalf1 reads h2(t-1)
            #pragma unroll
            for (int i = 0; i < 50; i += 5) {
                float2 cur[5];
                #pragma unroll
                for (int p = 0; p < 5; ++p) cur[p] = wb[p];
                #pragma unroll
                for (int p = 0; p < 5; ++p) {
                    const int nk = i + 5 + p;
                    if (nk < 50) wb[p] = __ldg(wp2 + (kb2 + nk) * Gdim);
                }
                #pragma unroll
                for (int p = 0; p < 5; ++p) {
                    const int k2 = kb2 + i + p;
                    const u64 w0 = pack2(cur[p].x), w1v = pack2(cur[p].y);
                    const u64x2 h0 = *(const u64x2*)(hb + 2*k2);
                    const u64x2 h1 = *(const u64x2*)(hb + 2*k2 + 1);
                    fma2(a0, w0,  h0.x); fma2(a1, w0,  h0.y);
                    fma2(a0, w1v, h1.x); fma2(a1, w1v, h1.y);
                }
            }
        }
        // ---- combine + cell (h2 -> hCur) ----
        a0 = add2(a0, __shfl_xor_sync(0xffffffffu, a0, 1));
        a1 = add2(a1, __shfl_xor_sync(0xffffffffu, a1, 1));
        __syncwarp();
        if (!khalf) {
            float f0,f1,f2,f3; unpack2(a0,f0,f1); unpack2(a1,f2,f3);
            gexw[l >> 1] = make_float4(f0,f1,f2,f3);
        }
        __syncwarp();
        if (l < 16) {
            const float* gw = (const float*)(gexw + ul * 4);
            const float vi = gw[ 0 + bl], vf = gw[ 4 + bl];
            const float vg = gw[ 8 + bl], vo = gw[12 + bl];
            c2 = fmaf(sigfast(vf), c2, sigfast(vi) * tanhfast(vg));
            ((float*)hCur)[(Hdim + w*4 + ul)*4 + bl] = sigfast(vo) * tanhfast(c2);
        }
        __syncthreads();   // h2(t) ready

        // ---- y projection (warps 0-3), overlapped with next L1 in input phase ----
        if (tid < 128) {
            const int wb_ = tid >> 5, ll = tid & 31;
            float s = 0.f;
            #pragma unroll
            for (int j = 0; j < Hdim; j += 32) {
                const int jj = j + ll;
                if (jj < Hdim)
                    s = fmaf(((const float*)hCur)[(Hdim + jj)*4 + wb_], wlin[jj], s);
            }
            #pragma unroll
            for (int off = 16; off > 0; off >>= 1)
                s += __shfl_down_sync(0xffffffffu, s, off);
            if (ll == 0) {
                const float y = s + blin_r;
                out[(b0 + wb_) * T_TOT + t] = y;
                ((float*)ysv)[wb_] = y;
            }
        }
        if (t >= T_IN - 1) __syncthreads();   // ysv feeds next step's x

        float4* tmp = hPrev; hPrev = hCur; hCur = tmp;
    }
}

extern "C" void kernel_launch(void* const* d_in, const int* in_sizes, int n_in,
                              void* d_out, int out_size) {
    const float* input = (const float*)d_in[0];
    const float* W_ih1 = (const float*)d_in[1];
    const float* W_hh1 = (const float*)d_in[2];
    const float* b_ih1 = (const float*)d_in[3];
    const float* b_hh1 = (const float*)d_in[4];
    const float* W_ih2 = (const float*)d_in[5];
    const float* W_hh2 = (const float*)d_in[6];
    const float* b_ih2 = (const float*)d_in[7];
    const float* b_hh2 = (const float*)d_in[8];
    const float* W_lin = (const float*)d_in[9];
    const float* b_lin = (const float*)d_in[10];
    float* out = (float*)d_out;

    prep_weights<<<(150 * Gdim + 255) / 256, 256>>>(W_hh1, W_ih2, W_hh2,
                                                    W_ih1, b_ih1, b_hh1,
                                                    b_ih2, b_hh2);

    const int smem_bytes = 47304 * (int)sizeof(float);
    cudaFuncSetAttribute(lstm2_kernel,
                         cudaFuncAttributeMaxDynamicSharedMemorySize, smem_bytes);
    lstm2_kernel<<<NCTA, NTHR, smem_bytes>>>(input, W_lin, b_lin, out);
}

// round 6
// speedup vs baseline: 1.2517x; 1.2517x over previous
#include <cuda_runtime.h>

#define Hdim  100
#define Gdim  400
#define T_IN  1000
#define T_TOT 1300
#define NB    4
#define NCTA  128
#define NTHR  800

// Pre-packed transposed weights.
__device__ float2 g_W1P[50 * Gdim];    // W_hh1^T  [k2][g]  (k-pairs)
__device__ float4 g_W2Q[50 * Gdim];    // [W_ih2;W_hh2]^T [k4][g]  (k-quads)

__global__ void prep_weights(const float* __restrict__ W_hh1,
                             const float* __restrict__ W_ih2,
                             const float* __restrict__ W_hh2) {
    int i = blockIdx.x * blockDim.x + threadIdx.x;
    if (i >= 50 * Gdim) return;
    int kq = i / Gdim, g = i % Gdim;
    // W1: k-pair kq covers k = 2kq, 2kq+1  (k < 100)
    g_W1P[i] = make_float2(W_hh1[g*Hdim + 2*kq], W_hh1[g*Hdim + 2*kq + 1]);
    // W2: k-quad kq covers k = 4kq .. 4kq+3 (k < 200; k<100 -> W_ih2, else W_hh2)
    float4 v;
    {
        int k = 4 * kq;
        const float* src = (k < Hdim) ? (W_ih2 + g*Hdim + k) : (W_hh2 + g*Hdim + k - Hdim);
        v.x = src[0]; v.y = src[1]; v.z = src[2]; v.w = src[3];
    }
    g_W2Q[i] = v;
}

typedef unsigned long long u64;
typedef ulonglong2 u64x2;

__device__ __forceinline__ u64 pack2(float v) {
    u64 r; asm("mov.b64 %0, {%1, %1};" : "=l"(r) : "f"(v)); return r;
}
__device__ __forceinline__ void fma2(u64& a, u64 w, u64 h) {
    asm("fma.rn.f32x2 %0, %1, %2, %0;" : "+l"(a) : "l"(w), "l"(h));
}
__device__ __forceinline__ float tanhfast(float x) {
    float y; asm("tanh.approx.f32 %0, %1;" : "=f"(y) : "f"(x)); return y;
}
__device__ __forceinline__ float sigfast(float x) {
    return fmaf(0.5f, tanhfast(0.5f * x), 0.5f);
}

__global__ __launch_bounds__(NTHR, 1)
void lstm2_kernel(const float* __restrict__ input,
                  const float* __restrict__ W_ih1,
                  const float* __restrict__ b_ih1,
                  const float* __restrict__ b_hh1,
                  const float* __restrict__ b_ih2,
                  const float* __restrict__ b_hh2,
                  const float* __restrict__ W_lin,
                  const float* __restrict__ b_lin,
                  float* __restrict__ out)
{
    extern __shared__ float sm[];
    float2*     W1s    = (float2*)sm;                    // [50*400] W_hh1^T packed
    float4*     hcat   = (float4*)(sm + 40000);          // [200] (h1|h2) x 4 batches
    ulonglong2* gatesA = (ulonglong2*)(hcat + 200);      // [400] partial (half A)
    ulonglong2* gatesB = gatesA + Gdim;                  // [400] partial (half B)
    float4*     xin    = (float4*)(gatesB + Gdim);       // [1000] input, t-major
    float4*     ysv    = xin + T_IN;                     // [1]  autoregressive x
    float*      wlin   = (float*)(ysv + 1);              // [100]
    // floats: 40000 + 800 + 1600 + 1600 + 4000 + 4 + 100 = 48104 (192416 B)

    const int tid  = threadIdx.x;
    const int b0   = blockIdx.x * NB;
    const bool hA  = (tid < Gdim);
    const int  g   = hA ? tid : tid - Gdim;

    // ---- one-time init ----
    for (int i = tid; i < 50 * Gdim; i += NTHR) W1s[i] = g_W1P[i];
    for (int i = tid; i < NB * T_IN; i += NTHR) {        // xin[t][b]
        int t = i >> 2, b = i & 3;
        ((float*)xin)[i] = input[(b0 + b) * T_IN + t];
    }
    if (tid < Hdim) wlin[tid] = W_lin[tid];
    for (int i = tid; i < 200 * 4; i += NTHR) ((float*)hcat)[i] = 0.f;
    const float blin_r = __ldg(b_lin);

    // per-thread constants (bias/x-weight only applied by half A)
    const u64 bb1p = hA ? pack2(b_ih1[g] + b_hh1[g]) : 0ull;
    const u64 bb2p = hA ? pack2(b_ih2[g] + b_hh2[g]) : 0ull;
    const u64 wip  = hA ? pack2(W_ih1[g]) : 0ull;
    const int k2L1 = hA ? 0 : 25;    // layer-1 k-pair start (k: 0..49 / 50..99)
    const int k4L2 = hA ? 0 : 25;    // layer-2 k-quad start (k: 0..99 / 100..199)

    const int cj = tid >> 2;         // cell role (tid < 400)
    const int cb = tid & 3;
    float c1 = 0.f, c2 = 0.f;
    __syncthreads();

    for (int t = 0; t < T_TOT; ++t) {
        // ---- Layer 1 gate partials (W1 from smem, conflict-free) ----
        {
            const u64x2 xp = (t < T_IN) ? *(const u64x2*)(xin + t)
                                        : *(const u64x2*)ysv;
            u64 a0 = bb1p, a1 = bb1p;
            if (hA) { fma2(a0, wip, xp.x); fma2(a1, wip, xp.y); }
            const float2* wp = W1s + g;
            #pragma unroll 5
            for (int k2 = k2L1; k2 < k2L1 + 25; ++k2) {
                const float2 w  = wp[k2 * Gdim];                       // coalesced
                const u64 w0 = pack2(w.x), w1 = pack2(w.y);
                const u64x2 h0 = *(const u64x2*)(hcat + 2*k2);         // broadcast
                const u64x2 h1 = *(const u64x2*)(hcat + 2*k2 + 1);
                fma2(a0, w0, h0.x); fma2(a1, w0, h0.y);
                fma2(a0, w1, h1.x); fma2(a1, w1, h1.y);
            }
            ulonglong2 r; r.x = a0; r.y = a1;
            if (hA) gatesA[g] = r; else gatesB[g] = r;
        }
        __syncthreads();                                  // #1 gates ready

        // ---- Layer 1 cell update (c1 in registers) ----
        if (tid < Gdim) {
            const float* gA = (const float*)gatesA;
            const float* gB = (const float*)gatesB;
            const float vi = gA[(cj         )*4 + cb] + gB[(cj         )*4 + cb];
            const float vf = gA[(cj +   Hdim)*4 + cb] + gB[(cj +   Hdim)*4 + cb];
            const float vg = gA[(cj + 2*Hdim)*4 + cb] + gB[(cj + 2*Hdim)*4 + cb];
            const float vo = gA[(cj + 3*Hdim)*4 + cb] + gB[(cj + 3*Hdim)*4 + cb];
            c1 = fmaf(sigfast(vf), c1, sigfast(vi) * tanhfast(vg));
            ((float*)hcat)[cj*4 + cb] = sigfast(vo) * tanhfast(c1);
        }
        __syncthreads();                                  // #2 h1(t) ready

        // ---- Layer 2 gate partials: k-quad split, W2 via LDG.128 ----
        {
            u64 a0 = bb2p, a1 = bb2p;
            const float4* wp = g_W2Q + g;
            #pragma unroll 5
            for (int k4 = k4L2; k4 < k4L2 + 25; ++k4) {
                const float4 w = __ldg(wp + k4 * Gdim);                // LDG.128
                const u64 w0 = pack2(w.x), w1 = pack2(w.y);
                const u64 w2 = pack2(w.z), w3 = pack2(w.w);
                const u64x2 h0 = *(const u64x2*)(hcat + 4*k4);
                const u64x2 h1 = *(const u64x2*)(hcat + 4*k4 + 1);
                const u64x2 h2 = *(const u64x2*)(hcat + 4*k4 + 2);
                const u64x2 h3 = *(const u64x2*)(hcat + 4*k4 + 3);
                fma2(a0, w0, h0.x); fma2(a1, w0, h0.y);
                fma2(a0, w1, h1.x); fma2(a1, w1, h1.y);
                fma2(a0, w2, h2.x); fma2(a1, w2, h2.y);
                fma2(a0, w3, h3.x); fma2(a1, w3, h3.y);
            }
            ulonglong2 r; r.x = a0; r.y = a1;
            if (hA) gatesA[g] = r; else gatesB[g] = r;
        }
        __syncthreads();                                  // #3 gates ready

        // ---- Layer 2 cell update ----
        if (tid < Gdim) {
            const float* gA = (const float*)gatesA;
            const float* gB = (const float*)gatesB;
            const float vi = gA[(cj         )*4 + cb] + gB[(cj         )*4 + cb];
            const float vf = gA[(cj +   Hdim)*4 + cb] + gB[(cj +   Hdim)*4 + cb];
            const float vg = gA[(cj + 2*Hdim)*4 + cb] + gB[(cj + 2*Hdim)*4 + cb];
            const float vo = gA[(cj + 3*Hdim)*4 + cb] + gB[(cj + 3*Hdim)*4 + cb];
            c2 = fmaf(sigfast(vf), c2, sigfast(vi) * tanhfast(vg));
            ((float*)hcat)[(Hdim + cj)*4 + cb] = sigfast(vo) * tanhfast(c2);
        }
        __syncthreads();                                  // #4 h2(t) ready

        // ---- Output projection (warps 0-3); overlaps next L1 in teacher phase ----
        if (tid < 128) {
            const int w = tid >> 5, l = tid & 31;
            float s = 0.f;
            #pragma unroll
            for (int j = 0; j < Hdim; j += 32) {
                const int jj = j + l;
                if (jj < Hdim)
                    s = fmaf(((const float*)hcat)[(Hdim + jj)*4 + w], wlin[jj], s);
            }
            #pragma unroll
            for (int o = 16; o > 0; o >>= 1)
                s += __shfl_down_sync(0xffffffffu, s, o);
            if (l == 0) {
                const float y = s + blin_r;
                out[(b0 + w) * T_TOT + t] = y;
                ((float*)ysv)[w] = y;
            }
        }
        // ysv only feeds x when t+1 >= T_IN; otherwise let warps run ahead.
        if (t >= T_IN - 1) __syncthreads();
    }
}

extern "C" void kernel_launch(void* const* d_in, const int* in_sizes, int n_in,
                              void* d_out, int out_size) {
    const float* input = (const float*)d_in[0];
    const float* W_ih1 = (const float*)d_in[1];
    const float* W_hh1 = (const float*)d_in[2];
    const float* b_ih1 = (const float*)d_in[3];
    const float* b_hh1 = (const float*)d_in[4];
    const float* W_ih2 = (const float*)d_in[5];
    const float* W_hh2 = (const float*)d_in[6];
    const float* b_ih2 = (const float*)d_in[7];
    const float* b_hh2 = (const float*)d_in[8];
    const float* W_lin = (const float*)d_in[9];
    const float* b_lin = (const float*)d_in[10];
    float* out = (float*)d_out;

    prep_weights<<<(50 * Gdim + 255) / 256, 256>>>(W_hh1, W_ih2, W_hh2);

    const int smem_bytes = 48104 * (int)sizeof(float);
    cudaFuncSetAttribute(lstm2_kernel,
                         cudaFuncAttributeMaxDynamicSharedMemorySize, smem_bytes);
    lstm2_kernel<<<NCTA, NTHR, smem_bytes>>>(input, W_ih1, b_ih1, b_hh1,
                                             b_ih2, b_hh2, W_lin, b_lin, out);
}